// round 1
// baseline (speedup 1.0000x reference)
#include <cuda_runtime.h>
#include <math.h>

#define NMAX 200000
#define EMAX 600000
#define BMAX 10000
#define D 128

// ---------------- scratch (device globals; no allocation allowed) ----------------
__device__ float g_xh[NMAX * D];    // h_e (ELU(LN(GAT)))
__device__ float g_xt[NMAX * D];    // t_e
__device__ float g_tmp[NMAX * D];   // current xs = x @ W
__device__ float g_acc[NMAX * D];   // aggregation accumulator / neigh sum
__device__ float g_alS[NMAX * 2];
__device__ float g_alD[NMAX * 2];
__device__ float g_m[NMAX * 2];
__device__ float g_s[NMAX * 2];
__device__ float g_vdst[D];
__device__ float g_attn[NMAX];
__device__ float g_mB[BMAX];
__device__ float g_sB[BMAX];

// ---------------- helpers ----------------
__device__ __forceinline__ float lrelu(float x) { return x > 0.f ? x : 0.2f * x; }

__device__ __forceinline__ void atomicMaxF(float* a, float v) {
    if (v >= 0.f) atomicMax((int*)a, __float_as_int(v));
    else          atomicMin((unsigned int*)a, __float_as_uint(v));
}

__device__ __forceinline__ float warp_sum(float v) {
#pragma unroll
    for (int o = 16; o > 0; o >>= 1) v += __shfl_xor_sync(0xffffffffu, v, o);
    return v;  // all lanes hold the total
}

// ---------------- GEMM: C[n x 128] = A[n x K] @ W[K x 128] (+bias | +=) ----------------
template <int K>
__global__ void __launch_bounds__(256, 2)
gemm_kernel(const float* __restrict__ A, const float* __restrict__ W,
            const float* __restrict__ bias, float* __restrict__ C,
            int n, int accumulate) {
    __shared__ __align__(16) float sA[32][128];  // transposed A tile
    __shared__ __align__(16) float sB[32][128];
    const int row0 = blockIdx.x * 128;
    const int tid = threadIdx.x;
    const int tx = tid & 15, ty = tid >> 4;

    float acc[8][8];
#pragma unroll
    for (int i = 0; i < 8; i++)
#pragma unroll
        for (int j = 0; j < 8; j++) acc[i][j] = 0.f;

    for (int k0 = 0; k0 < K; k0 += 32) {
        // load A tile (128 rows x 32 cols), store transposed
#pragma unroll
        for (int i = 0; i < 4; i++) {
            int L = i * 256 + tid;            // float4 index, 1024 total
            int r = L >> 3;
            int kk = (L & 7) << 2;
            float4 v = make_float4(0.f, 0.f, 0.f, 0.f);
            int gr = row0 + r;
            if (gr < n) v = *reinterpret_cast<const float4*>(A + (size_t)gr * K + k0 + kk);
            sA[kk + 0][r] = v.x; sA[kk + 1][r] = v.y;
            sA[kk + 2][r] = v.z; sA[kk + 3][r] = v.w;
        }
        // load W tile (32 rows x 128 cols)
#pragma unroll
        for (int i = 0; i < 4; i++) {
            int L = i * 256 + tid;
            int r = L >> 5;
            int cc = (L & 31) << 2;
            float4 v = *reinterpret_cast<const float4*>(W + (size_t)(k0 + r) * D + cc);
            *reinterpret_cast<float4*>(&sB[r][cc]) = v;
        }
        __syncthreads();
#pragma unroll
        for (int k = 0; k < 32; k++) {
            float a[8], b[8];
            float4 a0 = *reinterpret_cast<const float4*>(&sA[k][ty * 8]);
            float4 a1 = *reinterpret_cast<const float4*>(&sA[k][ty * 8 + 4]);
            a[0] = a0.x; a[1] = a0.y; a[2] = a0.z; a[3] = a0.w;
            a[4] = a1.x; a[5] = a1.y; a[6] = a1.z; a[7] = a1.w;
#pragma unroll
            for (int j = 0; j < 8; j++) b[j] = sB[k][tx + 16 * j];
#pragma unroll
            for (int i = 0; i < 8; i++)
#pragma unroll
                for (int j = 0; j < 8; j++) acc[i][j] += a[i] * b[j];
        }
        __syncthreads();
    }
#pragma unroll
    for (int i = 0; i < 8; i++) {
        int gr = row0 + ty * 8 + i;
        if (gr >= n) continue;
        float* cp = C + (size_t)gr * D;
#pragma unroll
        for (int j = 0; j < 8; j++) {
            int c = tx + 16 * j;
            float v = acc[i][j];
            if (accumulate) v += cp[c];
            else if (bias)  v += __ldg(bias + c);
            cp[c] = v;
        }
    }
}

// ---------------- node prep, 2-head (stage 1; self loops) ----------------
__global__ void node_prep2(const float* __restrict__ xs,
                           const float* __restrict__ a_src, const float* __restrict__ a_dst,
                           float* alS, float* alD, float* m, float* s, int n) {
    int warp = (blockIdx.x * blockDim.x + threadIdx.x) >> 5;
    int lane = threadIdx.x & 31;
    if (warp >= n) return;
    int c = lane * 4;
    float4 x  = *reinterpret_cast<const float4*>(xs + (size_t)warp * D + c);
    float4 as = *reinterpret_cast<const float4*>(a_src + c);
    float4 ad = *reinterpret_cast<const float4*>(a_dst + c);
    float ps = x.x * as.x + x.y * as.y + x.z * as.z + x.w * as.w;
    float pd = x.x * ad.x + x.y * ad.y + x.z * ad.z + x.w * ad.w;
#pragma unroll
    for (int o = 8; o > 0; o >>= 1) {
        ps += __shfl_down_sync(0xffffffffu, ps, o, 16);
        pd += __shfl_down_sync(0xffffffffu, pd, o, 16);
    }
    if ((lane & 15) == 0) {
        int h = lane >> 4;
        alS[warp * 2 + h] = ps;
        alD[warp * 2 + h] = pd;
        m[warp * 2 + h] = lrelu(ps + pd);  // self-loop logit seeds the max
        s[warp * 2 + h] = 0.f;
    }
}

// ---------------- node prep, 1-head ----------------
__global__ void node_prep1(const float* __restrict__ xsS, const float* __restrict__ vS,
                           const float* __restrict__ xsD, const float* __restrict__ vD,
                           int selfloop, float* alS, float* alD, float* m, float* s, int n) {
    int warp = (blockIdx.x * blockDim.x + threadIdx.x) >> 5;
    int lane = threadIdx.x & 31;
    if (warp >= n) return;
    int c = lane * 4;
    float4 xa = *reinterpret_cast<const float4*>(xsS + (size_t)warp * D + c);
    float4 va = *reinterpret_cast<const float4*>(vS + c);
    float4 xb = *reinterpret_cast<const float4*>(xsD + (size_t)warp * D + c);
    float4 vb = *reinterpret_cast<const float4*>(vD + c);
    float ps = xa.x * va.x + xa.y * va.y + xa.z * va.z + xa.w * va.w;
    float pd = xb.x * vb.x + xb.y * vb.y + xb.z * vb.z + xb.w * vb.w;
    ps = warp_sum(ps);
    pd = warp_sum(pd);
    if (lane == 0) {
        alS[warp] = ps;
        alD[warp] = pd;
        m[warp] = selfloop ? lrelu(ps + pd) : -INFINITY;
        s[warp] = 0.f;
    }
}

// ---------------- edge max ----------------
__global__ void edge_max2(const int* __restrict__ src, const int* __restrict__ dst,
                          const float* __restrict__ alS, const float* __restrict__ alD,
                          float* m, int E) {
    int e = blockIdx.x * blockDim.x + threadIdx.x;
    if (e >= E) return;
    int u = src[e], v = dst[e];
    atomicMaxF(&m[v * 2 + 0], lrelu(alS[u * 2 + 0] + alD[v * 2 + 0]));
    atomicMaxF(&m[v * 2 + 1], lrelu(alS[u * 2 + 1] + alD[v * 2 + 1]));
}

__global__ void edge_max1(const int* __restrict__ src, const int* __restrict__ dst,
                          const float* __restrict__ alS, const float* __restrict__ alD,
                          float* m, int E) {
    int e = blockIdx.x * blockDim.x + threadIdx.x;
    if (e >= E) return;
    int u = src[e], v = dst[e];
    atomicMaxF(&m[v], lrelu(alS[u] + alD[v]));
}

// ---------------- edge aggregate (unnormalized) ----------------
__global__ void edge_agg2(const int* __restrict__ src, const int* __restrict__ dst,
                          const float* __restrict__ alS, const float* __restrict__ alD,
                          const float* __restrict__ m, float* s,
                          const float* __restrict__ xs, float* acc, int E) {
    int warp = (blockIdx.x * blockDim.x + threadIdx.x) >> 5;
    int lane = threadIdx.x & 31;
    if (warp >= E) return;
    int u = src[warp], v = dst[warp];
    int h = lane >> 4;
    float w = 0.f;
    if ((lane & 15) == 0) {
        float e = lrelu(alS[u * 2 + h] + alD[v * 2 + h]);
        w = __expf(e - m[v * 2 + h]);
        atomicAdd(&s[v * 2 + h], w);
    }
    w = __shfl_sync(0xffffffffu, w, lane & 16);
    int c = lane * 4;  // col 0..127; head boundary at 64 matches lane 16
    float4 x = *reinterpret_cast<const float4*>(xs + (size_t)u * D + c);
    float* o = acc + (size_t)v * D + c;
    atomicAdd(o + 0, w * x.x); atomicAdd(o + 1, w * x.y);
    atomicAdd(o + 2, w * x.z); atomicAdd(o + 3, w * x.w);
}

__global__ void edge_agg1(const int* __restrict__ src, const int* __restrict__ dst,
                          const float* __restrict__ alS, const float* __restrict__ alD,
                          const float* __restrict__ m, float* s,
                          const float* __restrict__ xs, float* acc, int E) {
    int warp = (blockIdx.x * blockDim.x + threadIdx.x) >> 5;
    int lane = threadIdx.x & 31;
    if (warp >= E) return;
    int u = src[warp], v = dst[warp];
    float w = 0.f;
    if (lane == 0) {
        float e = lrelu(alS[u] + alD[v]);
        w = __expf(e - m[v]);
        atomicAdd(&s[v], w);
    }
    w = __shfl_sync(0xffffffffu, w, 0);
    int c = lane * 4;
    float4 x = *reinterpret_cast<const float4*>(xs + (size_t)u * D + c);
    float* o = acc + (size_t)v * D + c;
    atomicAdd(o + 0, w * x.x); atomicAdd(o + 1, w * x.y);
    atomicAdd(o + 2, w * x.z); atomicAdd(o + 3, w * x.w);
}

// ---------------- finalize stage 1: normalize + bias + LayerNorm + ELU ----------------
__global__ void fin_stage1(const float* __restrict__ acc, const float* __restrict__ xs,
                           const float* __restrict__ alS, const float* __restrict__ alD,
                           const float* __restrict__ m, const float* __restrict__ s,
                           const float* __restrict__ bgat, const float* __restrict__ g,
                           const float* __restrict__ bb, float* __restrict__ out, int n) {
    int warp = (blockIdx.x * blockDim.x + threadIdx.x) >> 5;
    int lane = threadIdx.x & 31;
    if (warp >= n) return;
    int h = lane >> 4;
    int c = lane * 4;
    float e  = lrelu(alS[warp * 2 + h] + alD[warp * 2 + h]);
    float ws = __expf(e - m[warp * 2 + h]);
    float inv = 1.f / (s[warp * 2 + h] + ws + 1e-16f);
    float4 A = *reinterpret_cast<const float4*>(acc + (size_t)warp * D + c);
    float4 X = *reinterpret_cast<const float4*>(xs + (size_t)warp * D + c);
    float4 Bt = *reinterpret_cast<const float4*>(bgat + c);
    float4 val;
    val.x = (A.x + ws * X.x) * inv + Bt.x;
    val.y = (A.y + ws * X.y) * inv + Bt.y;
    val.z = (A.z + ws * X.z) * inv + Bt.z;
    val.w = (A.w + ws * X.w) * inv + Bt.w;
    float sum = warp_sum(val.x + val.y + val.z + val.w);
    float sq  = warp_sum(val.x * val.x + val.y * val.y + val.z * val.z + val.w * val.w);
    float mu = sum * (1.f / 128.f);
    float var = sq * (1.f / 128.f) - mu * mu;
    float r = rsqrtf(var + 1e-5f);
    float4 gg = *reinterpret_cast<const float4*>(g + c);
    float4 bv = *reinterpret_cast<const float4*>(bb + c);
    float4 y;
    y.x = (val.x - mu) * r * gg.x + bv.x;
    y.y = (val.y - mu) * r * gg.y + bv.y;
    y.z = (val.z - mu) * r * gg.z + bv.z;
    y.w = (val.w - mu) * r * gg.w + bv.w;
    y.x = y.x > 0.f ? y.x : expm1f(y.x);
    y.y = y.y > 0.f ? y.y : expm1f(y.y);
    y.z = y.z > 0.f ? y.z : expm1f(y.z);
    y.w = y.w > 0.f ? y.w : expm1f(y.w);
    *reinterpret_cast<float4*>(out + (size_t)warp * D + c) = y;
}

// ---------------- finalize 1-head GAT in place ----------------
__global__ void fin1(float* __restrict__ out, const float* __restrict__ xs,
                     const float* __restrict__ alS, const float* __restrict__ alD,
                     const float* __restrict__ m, const float* __restrict__ s,
                     const float* __restrict__ bias, int selfloop, int n) {
    int warp = (blockIdx.x * blockDim.x + threadIdx.x) >> 5;
    int lane = threadIdx.x & 31;
    if (warp >= n) return;
    int c = lane * 4;
    float ws = 0.f, inv;
    if (selfloop) {
        float e = lrelu(alS[warp] + alD[warp]);
        ws = __expf(e - m[warp]);
        inv = 1.f / (s[warp] + ws + 1e-16f);
    } else {
        inv = 1.f / (s[warp] + 1e-16f);
    }
    float4 A = *reinterpret_cast<const float4*>(out + (size_t)warp * D + c);
    float4 X = *reinterpret_cast<const float4*>(xs + (size_t)warp * D + c);
    float4 Bv = *reinterpret_cast<const float4*>(bias + c);
    float4 y;
    y.x = (A.x + ws * X.x) * inv + Bv.x;
    y.y = (A.y + ws * X.y) * inv + Bv.y;
    y.z = (A.z + ws * X.z) * inv + Bv.z;
    y.w = (A.w + ws * X.w) * inv + Bv.w;
    *reinterpret_cast<float4*>(out + (size_t)warp * D + c) = y;
}

// ---------------- misc ----------------
__global__ void m_fixup(float* m, int n) {
    int i = blockIdx.x * blockDim.x + threadIdx.x;
    if (i < n && !isfinite(m[i])) m[i] = 0.f;
}

__global__ void compute_vdst(const float* __restrict__ Wd, const float* __restrict__ ad,
                             float* v) {
    int i = threadIdx.x;  // 128 threads
    float sum = 0.f;
    for (int j = 0; j < D; j++) sum += Wd[i * D + j] * ad[j];
    v[i] = sum;
}

// ---------------- SAG readout ----------------
__global__ void edge_neigh(const int* __restrict__ src, const int* __restrict__ dst,
                           const float* __restrict__ x, float* acc, int E) {
    int warp = (blockIdx.x * blockDim.x + threadIdx.x) >> 5;
    int lane = threadIdx.x & 31;
    if (warp >= E) return;
    int u = src[warp], v = dst[warp];
    int c = lane * 4;
    float4 xv = *reinterpret_cast<const float4*>(x + (size_t)u * D + c);
    float* o = acc + (size_t)v * D + c;
    atomicAdd(o + 0, xv.x); atomicAdd(o + 1, xv.y);
    atomicAdd(o + 2, xv.z); atomicAdd(o + 3, xv.w);
}

__global__ void attn_kernel(const float* __restrict__ neigh, const float* __restrict__ w_rel,
                            const float* __restrict__ b_rel, const float* __restrict__ x,
                            const float* __restrict__ w_root, float* attn, int n) {
    int warp = (blockIdx.x * blockDim.x + threadIdx.x) >> 5;
    int lane = threadIdx.x & 31;
    if (warp >= n) return;
    int c = lane * 4;
    float4 nv = *reinterpret_cast<const float4*>(neigh + (size_t)warp * D + c);
    float4 wr = *reinterpret_cast<const float4*>(w_rel + c);
    float4 xv = *reinterpret_cast<const float4*>(x + (size_t)warp * D + c);
    float4 wo = *reinterpret_cast<const float4*>(w_root + c);
    float p = nv.x * wr.x + nv.y * wr.y + nv.z * wr.z + nv.w * wr.w
            + xv.x * wo.x + xv.y * wo.y + xv.z * wo.z + xv.w * wo.w;
    p = warp_sum(p);
    if (lane == 0) attn[warp] = p + __ldg(b_rel);
}

__global__ void initB(float* mB, float* sB, int B) {
    int i = blockIdx.x * blockDim.x + threadIdx.x;
    if (i < B) { mB[i] = -INFINITY; sB[i] = 0.f; }
}

__global__ void batch_max(const float* __restrict__ attn, const int* __restrict__ batch,
                          float* mB, int n) {
    int i = blockIdx.x * blockDim.x + threadIdx.x;
    if (i >= n) return;
    atomicMaxF(&mB[batch[i]], attn[i]);
}

__global__ void batch_expsum(float* attn, const int* __restrict__ batch,
                             const float* __restrict__ mB, float* sB, int n) {
    int i = blockIdx.x * blockDim.x + threadIdx.x;
    if (i >= n) return;
    int g = batch[i];
    float w = __expf(attn[i] - mB[g]);
    attn[i] = w;
    atomicAdd(&sB[g], w);
}

__global__ void emb_agg(const float* __restrict__ x, const float* __restrict__ attn,
                        const int* __restrict__ batch, const float* __restrict__ sB,
                        float* emb, int n) {
    int warp = (blockIdx.x * blockDim.x + threadIdx.x) >> 5;
    int lane = threadIdx.x & 31;
    if (warp >= n) return;
    int g = batch[warp];
    float coef = attn[warp] / (sB[g] + 1e-16f);
    int c = lane * 4;
    float4 xv = *reinterpret_cast<const float4*>(x + (size_t)warp * D + c);
    float* o = emb + (size_t)g * D + c;
    atomicAdd(o + 0, coef * xv.x); atomicAdd(o + 1, coef * xv.y);
    atomicAdd(o + 2, coef * xv.z); atomicAdd(o + 3, coef * xv.w);
}

// ---------------- host orchestration ----------------
extern "C" void kernel_launch(void* const* d_in, const int* in_sizes, int n_in,
                              void* d_out, int out_size) {
    const float* h_x        = (const float*)d_in[0];
    const float* t_x        = (const float*)d_in[1];
    const float* W_gat      = (const float*)d_in[2];
    const float* a_src_gat  = (const float*)d_in[3];
    const float* a_dst_gat  = (const float*)d_in[4];
    const float* b_gat      = (const float*)d_in[5];
    const float* ln_g       = (const float*)d_in[6];
    const float* ln_b       = (const float*)d_in[7];
    const float* W_intra    = (const float*)d_in[8];
    const float* a_src_in   = (const float*)d_in[9];
    const float* a_dst_in   = (const float*)d_in[10];
    const float* b_intra    = (const float*)d_in[11];
    const float* W_int_src  = (const float*)d_in[12];
    const float* W_int_dst  = (const float*)d_in[13];
    const float* a_src_it   = (const float*)d_in[14];
    const float* a_dst_it   = (const float*)d_in[15];
    const float* b_inter    = (const float*)d_in[16];
    const float* W_reduce   = (const float*)d_in[17];
    const float* b_reduce   = (const float*)d_in[18];
    const float* w_rel      = (const float*)d_in[19];
    const float* b_rel      = (const float*)d_in[20];
    const float* w_root     = (const float*)d_in[21];
    const int*   h_ei       = (const int*)d_in[22];
    const int*   t_ei       = (const int*)d_in[23];
    const int*   b_ei       = (const int*)d_in[24];
    const int*   h_batch    = (const int*)d_in[25];
    const int*   t_batch    = (const int*)d_in[26];
    (void)n_in;

    const int N = in_sizes[0] / 64;
    const int E = in_sizes[22] / 2;
    const long long B = ((long long)out_size - 6LL * N * D) / (2 * D);

    float* out = (float*)d_out;
    const size_t NT = (size_t)N * D, BT = (size_t)B * D;
    float* h_fused = out;
    float* t_fused = out + NT;
    float* h_emb   = out + 2 * NT;
    float* t_emb   = h_emb + BT;
    float* h_intra = t_emb + BT;
    float* t_intra = h_intra + NT;
    float* h_inter = t_intra + NT;
    float* t_inter = h_inter + NT;

    float *xh, *xt, *tmp, *acc, *alS, *alD, *m, *s, *vdst, *attn, *mB, *sB;
    cudaGetSymbolAddress((void**)&xh,   g_xh);
    cudaGetSymbolAddress((void**)&xt,   g_xt);
    cudaGetSymbolAddress((void**)&tmp,  g_tmp);
    cudaGetSymbolAddress((void**)&acc,  g_acc);
    cudaGetSymbolAddress((void**)&alS,  g_alS);
    cudaGetSymbolAddress((void**)&alD,  g_alD);
    cudaGetSymbolAddress((void**)&m,    g_m);
    cudaGetSymbolAddress((void**)&s,    g_s);
    cudaGetSymbolAddress((void**)&vdst, g_vdst);
    cudaGetSymbolAddress((void**)&attn, g_attn);
    cudaGetSymbolAddress((void**)&mB,   g_mB);
    cudaGetSymbolAddress((void**)&sB,   g_sB);

    const int TB = 256;
    const int nbNodeW = (N + 7) / 8;       // warp-per-node
    const int nbEdgeW = (E + 7) / 8;       // warp-per-edge
    const int nbNodeT = (N + TB - 1) / TB; // thread-per-node
    const int nbEdgeT = (E + TB - 1) / TB;
    const int nbB     = ((int)B + TB - 1) / TB;
    const int nbGemm  = (N + 127) / 128;

    const int* h_src = h_ei;       const int* h_dst = h_ei + E;
    const int* t_src = t_ei;       const int* t_dst = t_ei + E;
    const int* b_src = b_ei;       const int* b_dst = b_ei + E;

    // ===== Stage 1: feature GAT + LN + ELU (h and t) =====
    {
        const float* xin[2] = { h_x, t_x };
        const int* esrc[2]  = { h_src, t_src };
        const int* edst[2]  = { h_dst, t_dst };
        float* xout[2]      = { xh, xt };
        for (int g2 = 0; g2 < 2; g2++) {
            gemm_kernel<64><<<nbGemm, TB>>>(xin[g2], W_gat, nullptr, tmp, N, 0);
            cudaMemsetAsync(acc, 0, NT * sizeof(float));
            node_prep2<<<nbNodeW, TB>>>(tmp, a_src_gat, a_dst_gat, alS, alD, m, s, N);
            edge_max2<<<nbEdgeT, TB>>>(esrc[g2], edst[g2], alS, alD, m, E);
            edge_agg2<<<nbEdgeW, TB>>>(esrc[g2], edst[g2], alS, alD, m, s, tmp, acc, E);
            fin_stage1<<<nbNodeW, TB>>>(acc, tmp, alS, alD, m, s, b_gat, ln_g, ln_b, xout[g2], N);
        }
    }

    // ===== Stage 2: intra GAT (1 head, self loops) =====
    {
        const float* xin[2] = { xh, xt };
        const int* esrc[2]  = { h_src, t_src };
        const int* edst[2]  = { h_dst, t_dst };
        float* oreg[2]      = { h_intra, t_intra };
        for (int g2 = 0; g2 < 2; g2++) {
            gemm_kernel<128><<<nbGemm, TB>>>(xin[g2], W_intra, nullptr, tmp, N, 0);
            cudaMemsetAsync(oreg[g2], 0, NT * sizeof(float));
            node_prep1<<<nbNodeW, TB>>>(tmp, a_src_in, tmp, a_dst_in, 1, alS, alD, m, s, N);
            edge_max1<<<nbEdgeT, TB>>>(esrc[g2], edst[g2], alS, alD, m, E);
            edge_agg1<<<nbEdgeW, TB>>>(esrc[g2], edst[g2], alS, alD, m, s, tmp, oreg[g2], E);
            fin1<<<nbNodeW, TB>>>(oreg[g2], tmp, alS, alD, m, s, b_intra, 1, N);
        }
    }

    // ===== Stage 3: inter (bipartite) GAT, no self loops =====
    compute_vdst<<<1, 128>>>(W_int_dst, a_dst_it, vdst);
    // t_inter: src side = h (xh), dst side = t (xt), edges b_src -> b_dst
    {
        gemm_kernel<128><<<nbGemm, TB>>>(xh, W_int_src, nullptr, tmp, N, 0);
        cudaMemsetAsync(t_inter, 0, NT * sizeof(float));
        node_prep1<<<nbNodeW, TB>>>(tmp, a_src_it, xt, vdst, 0, alS, alD, m, s, N);
        edge_max1<<<nbEdgeT, TB>>>(b_src, b_dst, alS, alD, m, E);
        m_fixup<<<nbNodeT, TB>>>(m, N);
        edge_agg1<<<nbEdgeW, TB>>>(b_src, b_dst, alS, alD, m, s, tmp, t_inter, E);
        fin1<<<nbNodeW, TB>>>(t_inter, tmp, alS, alD, m, s, b_inter, 0, N);
    }
    // h_inter: src side = t (xt), dst side = h (xh), edges b_dst -> b_src
    {
        gemm_kernel<128><<<nbGemm, TB>>>(xt, W_int_src, nullptr, tmp, N, 0);
        cudaMemsetAsync(h_inter, 0, NT * sizeof(float));
        node_prep1<<<nbNodeW, TB>>>(tmp, a_src_it, xh, vdst, 0, alS, alD, m, s, N);
        edge_max1<<<nbEdgeT, TB>>>(b_dst, b_src, alS, alD, m, E);
        m_fixup<<<nbNodeT, TB>>>(m, N);
        edge_agg1<<<nbEdgeW, TB>>>(b_dst, b_src, alS, alD, m, s, tmp, h_inter, E);
        fin1<<<nbNodeW, TB>>>(h_inter, tmp, alS, alD, m, s, b_inter, 0, N);
    }

    // ===== Stage 4: fused = [intra | inter] @ W_reduce + b_reduce =====
    gemm_kernel<128><<<nbGemm, TB>>>(h_intra, W_reduce, b_reduce, h_fused, N, 0);
    gemm_kernel<128><<<nbGemm, TB>>>(h_inter, W_reduce + 128 * D, nullptr, h_fused, N, 1);
    gemm_kernel<128><<<nbGemm, TB>>>(t_intra, W_reduce, b_reduce, t_fused, N, 0);
    gemm_kernel<128><<<nbGemm, TB>>>(t_inter, W_reduce + 128 * D, nullptr, t_fused, N, 1);

    // ===== Stage 5: SAG readout =====
    {
        const float* x[2]   = { h_fused, t_fused };
        const int* esrc[2]  = { h_src, t_src };
        const int* edst[2]  = { h_dst, t_dst };
        const int* batch[2] = { h_batch, t_batch };
        float* emb[2]       = { h_emb, t_emb };
        for (int g2 = 0; g2 < 2; g2++) {
            cudaMemsetAsync(acc, 0, NT * sizeof(float));
            edge_neigh<<<nbEdgeW, TB>>>(esrc[g2], edst[g2], x[g2], acc, E);
            attn_kernel<<<nbNodeW, TB>>>(acc, w_rel, b_rel, x[g2], w_root, attn, N);
            initB<<<nbB, TB>>>(mB, sB, (int)B);
            batch_max<<<nbNodeT, TB>>>(attn, batch[g2], mB, N);
            m_fixup<<<nbB, TB>>>(mB, (int)B);
            batch_expsum<<<nbNodeT, TB>>>(attn, batch[g2], mB, sB, N);
            cudaMemsetAsync(emb[g2], 0, BT * sizeof(float));
            emb_agg<<<nbNodeW, TB>>>(x[g2], attn, batch[g2], sB, emb[g2], N);
        }
    }
}

// round 2
// speedup vs baseline: 1.7274x; 1.7274x over previous
#include <cuda_runtime.h>
#include <math.h>

#define NMAX 200000
#define EMAX 600000
#define BMAX 10000
#define D 128

// ---------------- scratch (device globals; no allocation allowed) ----------------
__device__ float g_xh[NMAX * D];
__device__ float g_xt[NMAX * D];
__device__ float g_tmp[NMAX * D];
__device__ float g_acc[NMAX * D];
__device__ float g_alS[NMAX * 2];
__device__ float g_alD[NMAX * 2];
__device__ float g_m[NMAX * 2];
__device__ float g_s[NMAX * 2];
__device__ float g_vdst[D];
__device__ float g_attn[NMAX];
__device__ float g_mB[BMAX];
__device__ float g_sB[BMAX];

// ---------------- helpers ----------------
__device__ __forceinline__ float lrelu(float x) { return x > 0.f ? x : 0.2f * x; }

__device__ __forceinline__ void atomicMaxF(float* a, float v) {
    if (v >= 0.f) atomicMax((int*)a, __float_as_int(v));
    else          atomicMin((unsigned int*)a, __float_as_uint(v));
}

__device__ __forceinline__ float warp_sum(float v) {
#pragma unroll
    for (int o = 16; o > 0; o >>= 1) v += __shfl_xor_sync(0xffffffffu, v, o);
    return v;
}

__device__ __forceinline__ float to_tf32(float x) {
    float r;
    asm("cvt.rna.tf32.f32 %0, %1;" : "=f"(r) : "f"(x));
    return r;
}

__device__ __forceinline__ void mma_tf32(float* c, const unsigned* a, const unsigned* b) {
    asm volatile(
        "mma.sync.aligned.m16n8k8.row.col.f32.tf32.tf32.f32 "
        "{%0,%1,%2,%3}, {%4,%5,%6,%7}, {%8,%9}, {%0,%1,%2,%3};"
        : "+f"(c[0]), "+f"(c[1]), "+f"(c[2]), "+f"(c[3])
        : "r"(a[0]), "r"(a[1]), "r"(a[2]), "r"(a[3]), "r"(b[0]), "r"(b[1]));
}

__device__ __forceinline__ void redAdd4(float* p, float x, float y, float z, float w) {
    asm volatile("red.global.add.v4.f32 [%0], {%1,%2,%3,%4};"
                 :: "l"(p), "f"(x), "f"(y), "f"(z), "f"(w) : "memory");
}

// ---------------- TF32 tensor-core GEMM: C[n x 128] = A[n x K] @ W[K x 128] ----------------
template <int K>
__global__ void __launch_bounds__(256, 2)
gemm_tc(const float* __restrict__ A, const float* __restrict__ W,
        const float* __restrict__ bias, float* __restrict__ C,
        int n, int accumulate) {
    __shared__ __align__(16) float sA[128][36];   // pad 36: banks 4g+tig bijective
    __shared__ __align__(16) float sB[32][136];   // pad 136: banks 8tig+g bijective
    const int row0 = blockIdx.x * 128;
    const int tid = threadIdx.x;
    const int warp = tid >> 5, lane = tid & 31;
    const int wm = warp >> 1, wn = warp & 1;      // 4 x 2 warp grid -> 32x64 per warp
    const int g = lane >> 2, tig = lane & 3;

    float acc[2][8][4];
#pragma unroll
    for (int mt = 0; mt < 2; mt++)
#pragma unroll
        for (int nt = 0; nt < 8; nt++)
#pragma unroll
            for (int v = 0; v < 4; v++) acc[mt][nt][v] = 0.f;

    for (int k0 = 0; k0 < K; k0 += 32) {
#pragma unroll
        for (int i = 0; i < 4; i++) {            // A tile: 128 x 32
            int L = i * 256 + tid;
            int r = L >> 3, kc = (L & 7) << 2;
            float4 v = make_float4(0.f, 0.f, 0.f, 0.f);
            int gr = row0 + r;
            if (gr < n) v = *reinterpret_cast<const float4*>(A + (size_t)gr * K + k0 + kc);
            v.x = to_tf32(v.x); v.y = to_tf32(v.y); v.z = to_tf32(v.z); v.w = to_tf32(v.w);
            *reinterpret_cast<float4*>(&sA[r][kc]) = v;
        }
#pragma unroll
        for (int i = 0; i < 4; i++) {            // W tile: 32 x 128
            int L = i * 256 + tid;
            int r = L >> 5, cc = (L & 31) << 2;
            float4 v = *reinterpret_cast<const float4*>(W + (size_t)(k0 + r) * D + cc);
            v.x = to_tf32(v.x); v.y = to_tf32(v.y); v.z = to_tf32(v.z); v.w = to_tf32(v.w);
            *reinterpret_cast<float4*>(&sB[r][cc]) = v;
        }
        __syncthreads();
#pragma unroll
        for (int kk = 0; kk < 32; kk += 8) {
            unsigned af[2][4], bf[8][2];
#pragma unroll
            for (int mt = 0; mt < 2; mt++) {
                int rb = wm * 32 + mt * 16;
                af[mt][0] = __float_as_uint(sA[rb + g][kk + tig]);
                af[mt][1] = __float_as_uint(sA[rb + g + 8][kk + tig]);
                af[mt][2] = __float_as_uint(sA[rb + g][kk + tig + 4]);
                af[mt][3] = __float_as_uint(sA[rb + g + 8][kk + tig + 4]);
            }
#pragma unroll
            for (int nt = 0; nt < 8; nt++) {
                int cb = wn * 64 + nt * 8 + g;
                bf[nt][0] = __float_as_uint(sB[kk + tig][cb]);
                bf[nt][1] = __float_as_uint(sB[kk + tig + 4][cb]);
            }
#pragma unroll
            for (int mt = 0; mt < 2; mt++)
#pragma unroll
                for (int nt = 0; nt < 8; nt++)
                    mma_tf32(acc[mt][nt], af[mt], bf[nt]);
        }
        __syncthreads();
    }

#pragma unroll
    for (int mt = 0; mt < 2; mt++) {
        int r0 = row0 + wm * 32 + mt * 16 + g;
        int r1 = r0 + 8;
#pragma unroll
        for (int nt = 0; nt < 8; nt++) {
            int c = wn * 64 + nt * 8 + 2 * tig;
            if (r0 < n) {
                float* cp = C + (size_t)r0 * D + c;
                float v0 = acc[mt][nt][0], v1 = acc[mt][nt][1];
                if (accumulate) { v0 += cp[0]; v1 += cp[1]; }
                else if (bias)  { v0 += __ldg(bias + c); v1 += __ldg(bias + c + 1); }
                cp[0] = v0; cp[1] = v1;
            }
            if (r1 < n) {
                float* cp = C + (size_t)r1 * D + c;
                float v2 = acc[mt][nt][2], v3 = acc[mt][nt][3];
                if (accumulate) { v2 += cp[0]; v3 += cp[1]; }
                else if (bias)  { v2 += __ldg(bias + c); v3 += __ldg(bias + c + 1); }
                cp[0] = v2; cp[1] = v3;
            }
        }
    }
}

// ---------------- node prep, 2-head (stage 1; self loops) ----------------
__global__ void node_prep2(const float* __restrict__ xs,
                           const float* __restrict__ a_src, const float* __restrict__ a_dst,
                           float* alS, float* alD, float* m, float* s, int n) {
    int warp = (blockIdx.x * blockDim.x + threadIdx.x) >> 5;
    int lane = threadIdx.x & 31;
    if (warp >= n) return;
    int c = lane * 4;
    float4 x  = *reinterpret_cast<const float4*>(xs + (size_t)warp * D + c);
    float4 as = *reinterpret_cast<const float4*>(a_src + c);
    float4 ad = *reinterpret_cast<const float4*>(a_dst + c);
    float ps = x.x * as.x + x.y * as.y + x.z * as.z + x.w * as.w;
    float pd = x.x * ad.x + x.y * ad.y + x.z * ad.z + x.w * ad.w;
#pragma unroll
    for (int o = 8; o > 0; o >>= 1) {
        ps += __shfl_down_sync(0xffffffffu, ps, o, 16);
        pd += __shfl_down_sync(0xffffffffu, pd, o, 16);
    }
    if ((lane & 15) == 0) {
        int h = lane >> 4;
        alS[warp * 2 + h] = ps;
        alD[warp * 2 + h] = pd;
        m[warp * 2 + h] = lrelu(ps + pd);
        s[warp * 2 + h] = 0.f;
    }
}

// ---------------- node prep, 1-head ----------------
__global__ void node_prep1(const float* __restrict__ xsS, const float* __restrict__ vS,
                           const float* __restrict__ xsD, const float* __restrict__ vD,
                           int selfloop, float* alS, float* alD, float* m, float* s, int n) {
    int warp = (blockIdx.x * blockDim.x + threadIdx.x) >> 5;
    int lane = threadIdx.x & 31;
    if (warp >= n) return;
    int c = lane * 4;
    float4 xa = *reinterpret_cast<const float4*>(xsS + (size_t)warp * D + c);
    float4 va = *reinterpret_cast<const float4*>(vS + c);
    float4 xb = *reinterpret_cast<const float4*>(xsD + (size_t)warp * D + c);
    float4 vb = *reinterpret_cast<const float4*>(vD + c);
    float ps = xa.x * va.x + xa.y * va.y + xa.z * va.z + xa.w * va.w;
    float pd = xb.x * vb.x + xb.y * vb.y + xb.z * vb.z + xb.w * vb.w;
    ps = warp_sum(ps);
    pd = warp_sum(pd);
    if (lane == 0) {
        alS[warp] = ps;
        alD[warp] = pd;
        m[warp] = selfloop ? lrelu(ps + pd) : -INFINITY;
        s[warp] = 0.f;
    }
}

// ---------------- edge max ----------------
__global__ void edge_max2(const int* __restrict__ src, const int* __restrict__ dst,
                          const float* __restrict__ alS, const float* __restrict__ alD,
                          float* m, int E) {
    int e = blockIdx.x * blockDim.x + threadIdx.x;
    if (e >= E) return;
    int u = src[e], v = dst[e];
    atomicMaxF(&m[v * 2 + 0], lrelu(alS[u * 2 + 0] + alD[v * 2 + 0]));
    atomicMaxF(&m[v * 2 + 1], lrelu(alS[u * 2 + 1] + alD[v * 2 + 1]));
}

__global__ void edge_max1(const int* __restrict__ src, const int* __restrict__ dst,
                          const float* __restrict__ alS, const float* __restrict__ alD,
                          float* m, int E) {
    int e = blockIdx.x * blockDim.x + threadIdx.x;
    if (e >= E) return;
    int u = src[e], v = dst[e];
    atomicMaxF(&m[v], lrelu(alS[u] + alD[v]));
}

// ---------------- edge aggregate (unnormalized) ----------------
__global__ void edge_agg2(const int* __restrict__ src, const int* __restrict__ dst,
                          const float* __restrict__ alS, const float* __restrict__ alD,
                          const float* __restrict__ m, float* s,
                          const float* __restrict__ xs, float* acc, int E) {
    int warp = (blockIdx.x * blockDim.x + threadIdx.x) >> 5;
    int lane = threadIdx.x & 31;
    if (warp >= E) return;
    int u = src[warp], v = dst[warp];
    int h = lane >> 4;
    float w = 0.f;
    if ((lane & 15) == 0) {
        float e = lrelu(alS[u * 2 + h] + alD[v * 2 + h]);
        w = __expf(e - m[v * 2 + h]);
        atomicAdd(&s[v * 2 + h], w);
    }
    w = __shfl_sync(0xffffffffu, w, lane & 16);
    int c = lane * 4;
    float4 x = *reinterpret_cast<const float4*>(xs + (size_t)u * D + c);
    redAdd4(acc + (size_t)v * D + c, w * x.x, w * x.y, w * x.z, w * x.w);
}

__global__ void edge_agg1(const int* __restrict__ src, const int* __restrict__ dst,
                          const float* __restrict__ alS, const float* __restrict__ alD,
                          const float* __restrict__ m, float* s,
                          const float* __restrict__ xs, float* acc, int E) {
    int warp = (blockIdx.x * blockDim.x + threadIdx.x) >> 5;
    int lane = threadIdx.x & 31;
    if (warp >= E) return;
    int u = src[warp], v = dst[warp];
    float w = 0.f;
    if (lane == 0) {
        float e = lrelu(alS[u] + alD[v]);
        w = __expf(e - m[v]);
        atomicAdd(&s[v], w);
    }
    w = __shfl_sync(0xffffffffu, w, 0);
    int c = lane * 4;
    float4 x = *reinterpret_cast<const float4*>(xs + (size_t)u * D + c);
    redAdd4(acc + (size_t)v * D + c, w * x.x, w * x.y, w * x.z, w * x.w);
}

// ---------------- finalize stage 1: normalize + bias + LayerNorm + ELU ----------------
__global__ void fin_stage1(const float* __restrict__ acc, const float* __restrict__ xs,
                           const float* __restrict__ alS, const float* __restrict__ alD,
                           const float* __restrict__ m, const float* __restrict__ s,
                           const float* __restrict__ bgat, const float* __restrict__ g,
                           const float* __restrict__ bb, float* __restrict__ out, int n) {
    int warp = (blockIdx.x * blockDim.x + threadIdx.x) >> 5;
    int lane = threadIdx.x & 31;
    if (warp >= n) return;
    int h = lane >> 4;
    int c = lane * 4;
    float e  = lrelu(alS[warp * 2 + h] + alD[warp * 2 + h]);
    float ws = __expf(e - m[warp * 2 + h]);
    float inv = 1.f / (s[warp * 2 + h] + ws + 1e-16f);
    float4 A = *reinterpret_cast<const float4*>(acc + (size_t)warp * D + c);
    float4 X = *reinterpret_cast<const float4*>(xs + (size_t)warp * D + c);
    float4 Bt = *reinterpret_cast<const float4*>(bgat + c);
    float4 val;
    val.x = (A.x + ws * X.x) * inv + Bt.x;
    val.y = (A.y + ws * X.y) * inv + Bt.y;
    val.z = (A.z + ws * X.z) * inv + Bt.z;
    val.w = (A.w + ws * X.w) * inv + Bt.w;
    float sum = warp_sum(val.x + val.y + val.z + val.w);
    float sq  = warp_sum(val.x * val.x + val.y * val.y + val.z * val.z + val.w * val.w);
    float mu = sum * (1.f / 128.f);
    float var = sq * (1.f / 128.f) - mu * mu;
    float r = rsqrtf(var + 1e-5f);
    float4 gg = *reinterpret_cast<const float4*>(g + c);
    float4 bv = *reinterpret_cast<const float4*>(bb + c);
    float4 y;
    y.x = (val.x - mu) * r * gg.x + bv.x;
    y.y = (val.y - mu) * r * gg.y + bv.y;
    y.z = (val.z - mu) * r * gg.z + bv.z;
    y.w = (val.w - mu) * r * gg.w + bv.w;
    y.x = y.x > 0.f ? y.x : expm1f(y.x);
    y.y = y.y > 0.f ? y.y : expm1f(y.y);
    y.z = y.z > 0.f ? y.z : expm1f(y.z);
    y.w = y.w > 0.f ? y.w : expm1f(y.w);
    *reinterpret_cast<float4*>(out + (size_t)warp * D + c) = y;
}

// ---------------- finalize 1-head GAT in place ----------------
__global__ void fin1(float* __restrict__ out, const float* __restrict__ xs,
                     const float* __restrict__ alS, const float* __restrict__ alD,
                     const float* __restrict__ m, const float* __restrict__ s,
                     const float* __restrict__ bias, int selfloop, int n) {
    int warp = (blockIdx.x * blockDim.x + threadIdx.x) >> 5;
    int lane = threadIdx.x & 31;
    if (warp >= n) return;
    int c = lane * 4;
    float ws = 0.f, inv;
    if (selfloop) {
        float e = lrelu(alS[warp] + alD[warp]);
        ws = __expf(e - m[warp]);
        inv = 1.f / (s[warp] + ws + 1e-16f);
    } else {
        inv = 1.f / (s[warp] + 1e-16f);
    }
    float4 A = *reinterpret_cast<const float4*>(out + (size_t)warp * D + c);
    float4 X = *reinterpret_cast<const float4*>(xs + (size_t)warp * D + c);
    float4 Bv = *reinterpret_cast<const float4*>(bias + c);
    float4 y;
    y.x = (A.x + ws * X.x) * inv + Bv.x;
    y.y = (A.y + ws * X.y) * inv + Bv.y;
    y.z = (A.z + ws * X.z) * inv + Bv.z;
    y.w = (A.w + ws * X.w) * inv + Bv.w;
    *reinterpret_cast<float4*>(out + (size_t)warp * D + c) = y;
}

// ---------------- misc ----------------
__global__ void m_fixup(float* m, int n) {
    int i = blockIdx.x * blockDim.x + threadIdx.x;
    if (i < n && !isfinite(m[i])) m[i] = 0.f;
}

__global__ void compute_vdst(const float* __restrict__ Wd, const float* __restrict__ ad,
                             float* v) {
    int i = threadIdx.x;
    float sum = 0.f;
    for (int j = 0; j < D; j++) sum += Wd[i * D + j] * ad[j];
    v[i] = sum;
}

// ---------------- SAG readout ----------------
__global__ void edge_neigh(const int* __restrict__ src, const int* __restrict__ dst,
                           const float* __restrict__ x, float* acc, int E) {
    int warp = (blockIdx.x * blockDim.x + threadIdx.x) >> 5;
    int lane = threadIdx.x & 31;
    if (warp >= E) return;
    int u = src[warp], v = dst[warp];
    int c = lane * 4;
    float4 xv = *reinterpret_cast<const float4*>(x + (size_t)u * D + c);
    redAdd4(acc + (size_t)v * D + c, xv.x, xv.y, xv.z, xv.w);
}

__global__ void attn_kernel(const float* __restrict__ neigh, const float* __restrict__ w_rel,
                            const float* __restrict__ b_rel, const float* __restrict__ x,
                            const float* __restrict__ w_root, float* attn, int n) {
    int warp = (blockIdx.x * blockDim.x + threadIdx.x) >> 5;
    int lane = threadIdx.x & 31;
    if (warp >= n) return;
    int c = lane * 4;
    float4 nv = *reinterpret_cast<const float4*>(neigh + (size_t)warp * D + c);
    float4 wr = *reinterpret_cast<const float4*>(w_rel + c);
    float4 xv = *reinterpret_cast<const float4*>(x + (size_t)warp * D + c);
    float4 wo = *reinterpret_cast<const float4*>(w_root + c);
    float p = nv.x * wr.x + nv.y * wr.y + nv.z * wr.z + nv.w * wr.w
            + xv.x * wo.x + xv.y * wo.y + xv.z * wo.z + xv.w * wo.w;
    p = warp_sum(p);
    if (lane == 0) attn[warp] = p + __ldg(b_rel);
}

__global__ void initB(float* mB, float* sB, int B) {
    int i = blockIdx.x * blockDim.x + threadIdx.x;
    if (i < B) { mB[i] = -INFINITY; sB[i] = 0.f; }
}

__global__ void batch_max(const float* __restrict__ attn, const int* __restrict__ batch,
                          float* mB, int n) {
    int i = blockIdx.x * blockDim.x + threadIdx.x;
    if (i >= n) return;
    atomicMaxF(&mB[batch[i]], attn[i]);
}

__global__ void batch_expsum(float* attn, const int* __restrict__ batch,
                             const float* __restrict__ mB, float* sB, int n) {
    int i = blockIdx.x * blockDim.x + threadIdx.x;
    if (i >= n) return;
    int g = batch[i];
    float w = __expf(attn[i] - mB[g]);
    attn[i] = w;
    atomicAdd(&sB[g], w);
}

__global__ void emb_agg(const float* __restrict__ x, const float* __restrict__ attn,
                        const int* __restrict__ batch, const float* __restrict__ sB,
                        float* emb, int n) {
    int warp = (blockIdx.x * blockDim.x + threadIdx.x) >> 5;
    int lane = threadIdx.x & 31;
    if (warp >= n) return;
    int g = batch[warp];
    float coef = attn[warp] / (sB[g] + 1e-16f);
    int c = lane * 4;
    float4 xv = *reinterpret_cast<const float4*>(x + (size_t)warp * D + c);
    redAdd4(emb + (size_t)g * D + c, coef * xv.x, coef * xv.y, coef * xv.z, coef * xv.w);
}

// ---------------- host orchestration ----------------
extern "C" void kernel_launch(void* const* d_in, const int* in_sizes, int n_in,
                              void* d_out, int out_size) {
    const float* h_x        = (const float*)d_in[0];
    const float* t_x        = (const float*)d_in[1];
    const float* W_gat      = (const float*)d_in[2];
    const float* a_src_gat  = (const float*)d_in[3];
    const float* a_dst_gat  = (const float*)d_in[4];
    const float* b_gat      = (const float*)d_in[5];
    const float* ln_g       = (const float*)d_in[6];
    const float* ln_b       = (const float*)d_in[7];
    const float* W_intra    = (const float*)d_in[8];
    const float* a_src_in   = (const float*)d_in[9];
    const float* a_dst_in   = (const float*)d_in[10];
    const float* b_intra    = (const float*)d_in[11];
    const float* W_int_src  = (const float*)d_in[12];
    const float* W_int_dst  = (const float*)d_in[13];
    const float* a_src_it   = (const float*)d_in[14];
    const float* a_dst_it   = (const float*)d_in[15];
    const float* b_inter    = (const float*)d_in[16];
    const float* W_reduce   = (const float*)d_in[17];
    const float* b_reduce   = (const float*)d_in[18];
    const float* w_rel      = (const float*)d_in[19];
    const float* b_rel      = (const float*)d_in[20];
    const float* w_root     = (const float*)d_in[21];
    const int*   h_ei       = (const int*)d_in[22];
    const int*   t_ei       = (const int*)d_in[23];
    const int*   b_ei       = (const int*)d_in[24];
    const int*   h_batch    = (const int*)d_in[25];
    const int*   t_batch    = (const int*)d_in[26];
    (void)n_in;

    const int N = in_sizes[0] / 64;
    const int E = in_sizes[22] / 2;
    const long long B = ((long long)out_size - 6LL * N * D) / (2 * D);

    float* out = (float*)d_out;
    const size_t NT = (size_t)N * D, BT = (size_t)B * D;
    float* h_fused = out;
    float* t_fused = out + NT;
    float* h_emb   = out + 2 * NT;
    float* t_emb   = h_emb + BT;
    float* h_intra = t_emb + BT;
    float* t_intra = h_intra + NT;
    float* h_inter = t_intra + NT;
    float* t_inter = h_inter + NT;

    float *xh, *xt, *tmp, *acc, *alS, *alD, *m, *s, *vdst, *attn, *mB, *sB;
    cudaGetSymbolAddress((void**)&xh,   g_xh);
    cudaGetSymbolAddress((void**)&xt,   g_xt);
    cudaGetSymbolAddress((void**)&tmp,  g_tmp);
    cudaGetSymbolAddress((void**)&acc,  g_acc);
    cudaGetSymbolAddress((void**)&alS,  g_alS);
    cudaGetSymbolAddress((void**)&alD,  g_alD);
    cudaGetSymbolAddress((void**)&m,    g_m);
    cudaGetSymbolAddress((void**)&s,    g_s);
    cudaGetSymbolAddress((void**)&vdst, g_vdst);
    cudaGetSymbolAddress((void**)&attn, g_attn);
    cudaGetSymbolAddress((void**)&mB,   g_mB);
    cudaGetSymbolAddress((void**)&sB,   g_sB);

    const int TB = 256;
    const int nbNodeW = (N + 7) / 8;
    const int nbEdgeW = (E + 7) / 8;
    const int nbNodeT = (N + TB - 1) / TB;
    const int nbEdgeT = (E + TB - 1) / TB;
    const int nbB     = ((int)B + TB - 1) / TB;
    const int nbGemm  = (N + 127) / 128;

    const int* h_src = h_ei;       const int* h_dst = h_ei + E;
    const int* t_src = t_ei;       const int* t_dst = t_ei + E;
    const int* b_src = b_ei;       const int* b_dst = b_ei + E;

    // ===== Stage 1: feature GAT + LN + ELU (h and t) =====
    {
        const float* xin[2] = { h_x, t_x };
        const int* esrc[2]  = { h_src, t_src };
        const int* edst[2]  = { h_dst, t_dst };
        float* xout[2]      = { xh, xt };
        for (int g2 = 0; g2 < 2; g2++) {
            gemm_tc<64><<<nbGemm, TB>>>(xin[g2], W_gat, nullptr, tmp, N, 0);
            cudaMemsetAsync(acc, 0, NT * sizeof(float));
            node_prep2<<<nbNodeW, TB>>>(tmp, a_src_gat, a_dst_gat, alS, alD, m, s, N);
            edge_max2<<<nbEdgeT, TB>>>(esrc[g2], edst[g2], alS, alD, m, E);
            edge_agg2<<<nbEdgeW, TB>>>(esrc[g2], edst[g2], alS, alD, m, s, tmp, acc, E);
            fin_stage1<<<nbNodeW, TB>>>(acc, tmp, alS, alD, m, s, b_gat, ln_g, ln_b, xout[g2], N);
        }
    }

    // ===== Stage 2: intra GAT (1 head, self loops) =====
    {
        const float* xin[2] = { xh, xt };
        const int* esrc[2]  = { h_src, t_src };
        const int* edst[2]  = { h_dst, t_dst };
        float* oreg[2]      = { h_intra, t_intra };
        for (int g2 = 0; g2 < 2; g2++) {
            gemm_tc<128><<<nbGemm, TB>>>(xin[g2], W_intra, nullptr, tmp, N, 0);
            cudaMemsetAsync(oreg[g2], 0, NT * sizeof(float));
            node_prep1<<<nbNodeW, TB>>>(tmp, a_src_in, tmp, a_dst_in, 1, alS, alD, m, s, N);
            edge_max1<<<nbEdgeT, TB>>>(esrc[g2], edst[g2], alS, alD, m, E);
            edge_agg1<<<nbEdgeW, TB>>>(esrc[g2], edst[g2], alS, alD, m, s, tmp, oreg[g2], E);
            fin1<<<nbNodeW, TB>>>(oreg[g2], tmp, alS, alD, m, s, b_intra, 1, N);
        }
    }

    // ===== Stage 3: inter (bipartite) GAT, no self loops =====
    compute_vdst<<<1, 128>>>(W_int_dst, a_dst_it, vdst);
    {
        gemm_tc<128><<<nbGemm, TB>>>(xh, W_int_src, nullptr, tmp, N, 0);
        cudaMemsetAsync(t_inter, 0, NT * sizeof(float));
        node_prep1<<<nbNodeW, TB>>>(tmp, a_src_it, xt, vdst, 0, alS, alD, m, s, N);
        edge_max1<<<nbEdgeT, TB>>>(b_src, b_dst, alS, alD, m, E);
        m_fixup<<<nbNodeT, TB>>>(m, N);
        edge_agg1<<<nbEdgeW, TB>>>(b_src, b_dst, alS, alD, m, s, tmp, t_inter, E);
        fin1<<<nbNodeW, TB>>>(t_inter, tmp, alS, alD, m, s, b_inter, 0, N);
    }
    {
        gemm_tc<128><<<nbGemm, TB>>>(xt, W_int_src, nullptr, tmp, N, 0);
        cudaMemsetAsync(h_inter, 0, NT * sizeof(float));
        node_prep1<<<nbNodeW, TB>>>(tmp, a_src_it, xh, vdst, 0, alS, alD, m, s, N);
        edge_max1<<<nbEdgeT, TB>>>(b_dst, b_src, alS, alD, m, E);
        m_fixup<<<nbNodeT, TB>>>(m, N);
        edge_agg1<<<nbEdgeW, TB>>>(b_dst, b_src, alS, alD, m, s, tmp, h_inter, E);
        fin1<<<nbNodeW, TB>>>(h_inter, tmp, alS, alD, m, s, b_inter, 0, N);
    }

    // ===== Stage 4: fused = [intra | inter] @ W_reduce + b_reduce =====
    gemm_tc<128><<<nbGemm, TB>>>(h_intra, W_reduce, b_reduce, h_fused, N, 0);
    gemm_tc<128><<<nbGemm, TB>>>(h_inter, W_reduce + 128 * D, nullptr, h_fused, N, 1);
    gemm_tc<128><<<nbGemm, TB>>>(t_intra, W_reduce, b_reduce, t_fused, N, 0);
    gemm_tc<128><<<nbGemm, TB>>>(t_inter, W_reduce + 128 * D, nullptr, t_fused, N, 1);

    // ===== Stage 5: SAG readout =====
    {
        const float* x[2]   = { h_fused, t_fused };
        const int* esrc[2]  = { h_src, t_src };
        const int* edst[2]  = { h_dst, t_dst };
        const int* batch[2] = { h_batch, t_batch };
        float* emb[2]       = { h_emb, t_emb };
        for (int g2 = 0; g2 < 2; g2++) {
            cudaMemsetAsync(acc, 0, NT * sizeof(float));
            edge_neigh<<<nbEdgeW, TB>>>(esrc[g2], edst[g2], x[g2], acc, E);
            attn_kernel<<<nbNodeW, TB>>>(acc, w_rel, b_rel, x[g2], w_root, attn, N);
            initB<<<nbB, TB>>>(mB, sB, (int)B);
            batch_max<<<nbNodeT, TB>>>(attn, batch[g2], mB, N);
            m_fixup<<<nbB, TB>>>(mB, (int)B);
            batch_expsum<<<nbNodeT, TB>>>(attn, batch[g2], mB, sB, N);
            cudaMemsetAsync(emb[g2], 0, BT * sizeof(float));
            emb_agg<<<nbNodeW, TB>>>(x[g2], attn, batch[g2], sB, emb[g2], N);
        }
    }
}